// round 8
// baseline (speedup 1.0000x reference)
#include <cuda_runtime.h>
#include <cstdint>

typedef unsigned long long u64;
typedef unsigned int u32;

#define G_DIM 2048
#define T_DIM 16
#define B_DIM 256
#define P_DIM 64
#define ROWS_PER_G 51   // 3 classes x 17 rows

// Init-kernel block layout
#define NB_PACK   1024                    // params rows: 1024 blocks x 8 warps x 4 rows = 32768
#define NB_PV     8                       // param_vals rows: 8 x 8 x 4 = 256
#define NB_META   8                       // 8 x 256 = 2048 g's
#define NB_ROWS   408                     // 408 x 256 >= 2048*51
#define NB_TOTAL  (NB_PACK + NB_PV + NB_META + NB_ROWS)

// Device-global scratch (no allocations allowed)
__device__ u64  g_pv[B_DIM];
__device__ int4 g_terms[G_DIM * T_DIM];        // x=bits_lo, y=bits_hi, z=pw, w=pad
__device__ int2 g_meta[G_DIM];                 // x=s_pack,  y=m0
__device__ int4 g_rows[G_DIM * ROWS_PER_G];    // staged table rows per g

// ---------------------------------------------------------------------------
// Ring ops in basis (1, w, w^2, w^3), w^4 = -1.
// ---------------------------------------------------------------------------
__device__ __forceinline__ void ringmul(int* z, const int* x, const int* y) {
    z[0] = x[0]*y[0] - x[1]*y[3] - x[2]*y[2] - x[3]*y[1];
    z[1] = x[0]*y[1] + x[1]*y[0] - x[2]*y[3] - x[3]*y[2];
    z[2] = x[0]*y[2] + x[1]*y[1] + x[2]*y[0] - x[3]*y[3];
    z[3] = x[0]*y[3] + x[1]*y[2] + x[2]*y[1] + x[3]*y[0];
}
__device__ __forceinline__ void ringcpy(int* d, const int* s) {
    d[0] = s[0]; d[1] = s[1]; d[2] = s[2]; d[3] = s[3];
}
__device__ __forceinline__ void ringpow(int* acc, const int* f, int n) {
    int base[4], tmp[4];
    acc[0] = 1; acc[1] = 0; acc[2] = 0; acc[3] = 0;
    ringcpy(base, f);
    while (n) {
        if (n & 1) { ringmul(tmp, acc, base); ringcpy(acc, tmp); }
        n >>= 1;
        if (n) { ringmul(tmp, base, base); ringcpy(base, tmp); }
    }
}

__device__ __forceinline__ int clamp_cnt(int c) {
    return c < 0 ? 0 : (c > T_DIM ? T_DIM : c);
}

// ---------------------------------------------------------------------------
// ONE init kernel, heterogeneous blocks (see NB_* layout above).
// ---------------------------------------------------------------------------
__global__ void init_kernel(const int* __restrict__ params,
                            const int* __restrict__ phases,
                            const int* __restrict__ counts,
                            const int* __restrict__ param_vals) {
    const int bid = blockIdx.x;
    const int tid = threadIdx.x;

    if (bid < NB_PACK) {                   // ---- params pack: all 32768 rows ----
        int warp = tid >> 5, lane = tid & 31;
        int row0 = (bid * 8 + warp) * 4;
        int a[4], b[4];
        #pragma unroll
        for (int r = 0; r < 4; r++) {
            const int* p = params + (size_t)(row0 + r) * P_DIM;
            a[r] = p[lane]; b[r] = p[lane + 32];
        }
        #pragma unroll
        for (int r = 0; r < 4; r++) {
            u32 lo = __ballot_sync(0xffffffffu, a[r] & 1);
            u32 hi = __ballot_sync(0xffffffffu, b[r] & 1);
            if (lane == 0)
                *(int2*)&g_terms[row0 + r] = make_int2((int)lo, (int)hi);
        }
    } else if (bid < NB_PACK + NB_PV) {    // ---- param_vals pack: 256 rows ----
        int warp = tid >> 5, lane = tid & 31;
        int row0 = ((bid - NB_PACK) * 8 + warp) * 4;
        int a[4], b[4];
        #pragma unroll
        for (int r = 0; r < 4; r++) {
            const int* p = param_vals + (size_t)(row0 + r) * P_DIM;
            a[r] = p[lane]; b[r] = p[lane + 32];
        }
        #pragma unroll
        for (int r = 0; r < 4; r++) {
            u32 lo = __ballot_sync(0xffffffffu, a[r] & 1);
            u32 hi = __ballot_sync(0xffffffffu, b[r] & 1);
            if (lane == 0)
                g_pv[row0 + r] = ((u64)hi << 32) | (u64)lo;
        }
    } else if (bid < NB_PACK + NB_PV + NB_META) {   // ---- per-g meta + pw ----
        int g = (bid - NB_PACK - NB_PV) * 256 + tid;
        int c = clamp_cnt(counts[g]);
        int s0 = 0, s1 = 0, s2 = 0, s3 = 0, m0 = 0;
        #pragma unroll
        for (int t = 0; t < T_DIM; t++) {
            int p = phases[g * T_DIM + t] & 7;
            int k = p & 3, sg = (p >> 2) & 1;
            int valid = (t < c) ? 1 : 0;
            int pw = valid ? (sg ? -(1 << (8 * k)) : (1 << (8 * k))) : 0;
            g_terms[g * T_DIM + t].z = pw;
            int vs = valid & sg;
            s0 += vs & (k == 0); s1 += vs & (k == 1);
            s2 += vs & (k == 2); s3 += vs & (k == 3);
            m0 += valid & (k == 0);
        }
        g_meta[g] = make_int2(s0 | (s1 << 8) | (s2 << 16) | (s3 << 24), m0);
    } else {                               // ---- staged table rows ----
        int e = (bid - NB_PACK - NB_PV - NB_META) * 256 + tid;
        if (e < G_DIM * ROWS_PER_G) {
            int g = e / ROWS_PER_G;
            int r = e % ROWS_PER_G;
            int k = r / 17, b = r % 17;
            int kk = k + 1;
            int c = clamp_cnt(counts[g]);
            int m = 0;
            #pragma unroll
            for (int t = 0; t < T_DIM; t++) {
                int p = phases[g * T_DIM + t] & 7;
                m += (t < c) & ((p & 3) == kk);
            }
            int4 out;
            if (b > m) {
                out = make_int4(0, 0, 0, 0);
            } else {
                int fp[4] = {1, 0, 0, 0}; fp[kk] = 1;    // 1 + w^kk
                int fm[4] = {1, 0, 0, 0}; fm[kk] = -1;   // 1 - w^kk
                int pa[4], pb[4], acc[4];
                ringpow(pa, fp, m - b);
                ringpow(pb, fm, b);
                ringmul(acc, pa, pb);
                out = make_int4(acc[0], acc[1], acc[2], acc[3]);
            }
            g_rows[g * ROWS_PER_G + k * 17 + b] = out;
        }
    }
}

// ---------------------------------------------------------------------------
// Main kernel: grid 1024 x 256 threads; block handles g0 = 2*blockIdx.x and
// g0+1 for all 256 b's. No shared memory, no barriers, branch-free.
// Output float32 (B, G, 4); reference basis (1,w,w^2,w^7): c3 = -z3.
// ---------------------------------------------------------------------------
__global__ void __launch_bounds__(256)
nodephases_main_kernel(float* __restrict__ out) {
    const int g0  = blockIdx.x * 2;
    const int tid = threadIdx.x;

    const u64 v = g_pv[tid];
    const u32 vlo = (u32)v, vhi = (u32)(v >> 32);

    float4* ob = (float4*)out + (size_t)tid * G_DIM + g0;

    #pragma unroll
    for (int gi = 0; gi < 2; gi++) {
        const int g = g0 + gi;
        const int2 meta = *(const int2*)&g_meta[g];
        const int4* terms = g_terms + g * T_DIM;

        int cpA = meta.x;
        int cpB = 0x10101010;
        #pragma unroll
        for (int t = 0; t < 8; t++) {
            int4 tw = __ldg(&terms[t]);
            u32 x = ((u32)tw.x & vlo) ^ ((u32)tw.y & vhi);
            cpA += (int)(__popc(x) & 1u) * tw.z;
        }
        #pragma unroll
        for (int t = 8; t < 16; t++) {
            int4 tw = __ldg(&terms[t]);
            u32 x = ((u32)tw.x & vlo) ^ ((u32)tw.y & vhi);
            cpB += (int)(__popc(x) & 1u) * tw.z;
        }
        int cp = cpA + cpB - 0x10101010;

        int b0 = cp & 255;
        int b1 = (cp >> 8) & 255;
        int b2 = (cp >> 16) & 255;
        int b3 = (cp >> 24) & 255;

        const int4* rows = g_rows + g * ROWS_PER_G;
        int4 A = __ldg(&rows[b1]);
        int4 B = __ldg(&rows[17 + b2]);
        int4 C = __ldg(&rows[34 + b3]);

        int r0 = A.x*B.x - A.y*B.w - A.z*B.z - A.w*B.y;
        int r1 = A.x*B.y + A.y*B.x - A.z*B.w - A.w*B.z;
        int r2 = A.x*B.z + A.y*B.y + A.z*B.x - A.w*B.w;
        int r3 = A.x*B.w + A.y*B.z + A.z*B.y + A.w*B.x;

        int z0 = r0*C.x - r1*C.w - r2*C.z - r3*C.y;
        int z1 = r0*C.y + r1*C.x - r2*C.w - r3*C.z;
        int z2 = r0*C.z + r1*C.y + r2*C.x - r3*C.w;
        int z3 = r0*C.w + r1*C.z + r2*C.y + r3*C.x;

        int sc = (b0 == 0) ? (1 << meta.y) : 0;

        ob[gi] = make_float4((float)(z0 * sc), (float)(z1 * sc),
                             (float)(z2 * sc), (float)(-z3 * sc));
    }
}

// ---------------------------------------------------------------------------
// Launch. Inputs identified BY SIZE (ordering-proof):
//   phases 32768 | params 2097152 | counts 2048 | param_vals 16384 | opp 32
// ---------------------------------------------------------------------------
extern "C" void kernel_launch(void* const* d_in, const int* in_sizes, int n_in,
                              void* d_out, int out_size) {
    const int* phases = nullptr;
    const int* params = nullptr;
    const int* counts = nullptr;
    const int* param_vals = nullptr;

    for (int i = 0; i < n_in; i++) {
        switch (in_sizes[i]) {
            case G_DIM * T_DIM:         phases     = (const int*)d_in[i]; break;
            case G_DIM * T_DIM * P_DIM: params     = (const int*)d_in[i]; break;
            case G_DIM:                 counts     = (const int*)d_in[i]; break;
            case B_DIM * P_DIM:         param_vals = (const int*)d_in[i]; break;
            default: break;  // one_plus_phases (32 floats) — unused
        }
    }

    init_kernel<<<NB_TOTAL, 256>>>(params, phases, counts, param_vals);
    nodephases_main_kernel<<<G_DIM / 2, 256>>>((float*)d_out);
}

// round 9
// speedup vs baseline: 1.1271x; 1.1271x over previous
#include <cuda_runtime.h>
#include <cstdint>

typedef unsigned long long u64;
typedef unsigned int u32;

#define G_DIM 2048
#define T_DIM 16
#define B_DIM 256
#define P_DIM 64
#define G_PER_BLOCK 8
#define ROWS_PER_G 51   // 3 classes x 17 rows

// Device-global scratch (no allocations allowed)
__device__ u64 g_pv[B_DIM];

// ---------------------------------------------------------------------------
// Ring ops in basis (1, w, w^2, w^3), w^4 = -1.
// ---------------------------------------------------------------------------
__device__ __forceinline__ void ringmul(int* z, const int* x, const int* y) {
    z[0] = x[0]*y[0] - x[1]*y[3] - x[2]*y[2] - x[3]*y[1];
    z[1] = x[0]*y[1] + x[1]*y[0] - x[2]*y[3] - x[3]*y[2];
    z[2] = x[0]*y[2] + x[1]*y[1] + x[2]*y[0] - x[3]*y[3];
    z[3] = x[0]*y[3] + x[1]*y[2] + x[2]*y[1] + x[3]*y[0];
}
__device__ __forceinline__ void ringcpy(int* d, const int* s) {
    d[0] = s[0]; d[1] = s[1]; d[2] = s[2]; d[3] = s[3];
}
__device__ __forceinline__ void ringpow(int* acc, const int* f, int n) {
    int base[4], tmp[4];
    acc[0] = 1; acc[1] = 0; acc[2] = 0; acc[3] = 0;
    ringcpy(base, f);
    while (n) {
        if (n & 1) { ringmul(tmp, acc, base); ringcpy(acc, tmp); }
        n >>= 1;
        if (n) { ringmul(tmp, base, base); ringcpy(base, tmp); }
    }
}
__device__ __forceinline__ int clamp_cnt(int c) {
    return c < 0 ? 0 : (c > T_DIM ? T_DIM : c);
}

// ---------------------------------------------------------------------------
// Tiny pre-kernel: pack param_vals (256 rows x 64 int32 0/1) into u64 bitsets.
// 1 block x 256 threads; each warp packs 32 rows.
// ---------------------------------------------------------------------------
__global__ void pack_pv_kernel(const int* __restrict__ param_vals) {
    int warp = threadIdx.x >> 5, lane = threadIdx.x & 31;
    int row0 = warp * 32;
    for (int r = 0; r < 32; r++) {
        const int* p = param_vals + (size_t)(row0 + r) * P_DIM;
        u32 lo = __ballot_sync(0xffffffffu, p[lane] & 1);
        u32 hi = __ballot_sync(0xffffffffu, p[lane + 32] & 1);
        if (lane == 0) g_pv[row0 + r] = ((u64)hi << 32) | (u64)lo;
    }
}

// ---------------------------------------------------------------------------
// Main kernel: 256 blocks x 256 threads. Block handles g0..g0+7 for all 256 b.
// Prologue (one barrier total):
//   - warp w: ballot-packs g=g0+w's 16 param rows into s_term[w][t].{x,y}
//             and computes meta (s_pack, m0) + per-term pw -> s_term[w][t].z
//   - all threads: stage table rows s_rows[gi][k*17+b] = (1+w^k)^(m-b)(1-w^k)^b
//     via ringpow (m recomputed from phases; independent of pack/meta).
// Compute: per g, branch-free packed-byte-counter parity + 3 LDS row lookups
//          + 2 ring multiplies; result * ((b0==0) ? 2^m0 : 0).
// Output float32 (B, G, 4) in reference basis (1,w,w^2,w^7): c3 = -z3.
// ---------------------------------------------------------------------------
__global__ void __launch_bounds__(256)
nodephases_main_kernel(const int* __restrict__ params,
                       const int* __restrict__ phases,
                       const int* __restrict__ counts,
                       float* __restrict__ out) {
    const int g0   = blockIdx.x * G_PER_BLOCK;
    const int tid  = threadIdx.x;
    const int lane = tid & 31;
    const int warp = tid >> 5;

    __shared__ int4 s_term[G_PER_BLOCK][T_DIM];        // x=lo, y=hi, z=pw
    __shared__ int4 s_rows[G_PER_BLOCK][ROWS_PER_G];   // staged table rows
    __shared__ int2 s_meta[G_PER_BLOCK];               // x=s_pack, y=m0

    // ---- pack: warp w handles g = g0 + w ----
    {
        const int g = g0 + warp;
        const int* pr = params + (size_t)g * (T_DIM * P_DIM);
        #pragma unroll
        for (int t = 0; t < T_DIM; t++) {
            u32 lo = __ballot_sync(0xffffffffu, pr[t * P_DIM + lane] & 1);
            u32 hi = __ballot_sync(0xffffffffu, pr[t * P_DIM + 32 + lane] & 1);
            if (lane == 0) { s_term[warp][t].x = (int)lo; s_term[warp][t].y = (int)hi; }
        }
        // meta + pw
        int c = clamp_cnt(counts[g]);
        u32 vm = (c >= 16) ? 0xFFFFu : ((1u << c) - 1u);
        int p  = (lane < 16) ? (phases[g * T_DIM + lane] & 7) : 0;
        int k  = p & 3;
        int sg = (p >> 2) & 1;
        u32 b0m = __ballot_sync(0xffffffffu, k == 0) & vm;
        u32 sgm = __ballot_sync(0xffffffffu, sg == 1) & vm;
        u32 b1m = __ballot_sync(0xffffffffu, k == 1) & vm;
        u32 b2m = __ballot_sync(0xffffffffu, k == 2) & vm;
        u32 b3m = __ballot_sync(0xffffffffu, k == 3) & vm;
        if (lane < 16) {
            int valid = (vm >> lane) & 1;
            s_term[warp][lane].z = valid ? (sg ? -(1 << (8 * k)) : (1 << (8 * k))) : 0;
        }
        if (lane == 0) {
            int s0 = __popc(b0m & sgm), s1 = __popc(b1m & sgm),
                s2 = __popc(b2m & sgm), s3 = __popc(b3m & sgm);
            s_meta[warp] = make_int2(s0 | (s1 << 8) | (s2 << 16) | (s3 << 24),
                                     __popc(b0m));
        }
    }

    // ---- stage table rows: units (gi, k, b), independent of pack/meta ----
    for (int u = tid; u < G_PER_BLOCK * ROWS_PER_G; u += 256) {
        int gi = u / ROWS_PER_G;
        int r  = u % ROWS_PER_G;
        int k  = r / 17, b = r % 17;
        int kk = k + 1;
        int g  = g0 + gi;
        int c  = clamp_cnt(counts[g]);
        int m = 0;
        #pragma unroll
        for (int t = 0; t < T_DIM; t++) {
            int p = phases[g * T_DIM + t] & 7;
            m += (int)((t < c) & ((p & 3) == kk));
        }
        int4 o;
        if (b > m) {
            o = make_int4(0, 0, 0, 0);
        } else {
            int fp[4] = {1, 0, 0, 0}; fp[kk] = 1;    // 1 + w^kk
            int fm[4] = {1, 0, 0, 0}; fm[kk] = -1;   // 1 - w^kk
            int pa[4], pb[4], acc[4];
            ringpow(pa, fp, m - b);
            ringpow(pb, fm, b);
            ringmul(acc, pa, pb);
            o = make_int4(acc[0], acc[1], acc[2], acc[3]);
        }
        s_rows[gi][r] = o;
    }

    __syncthreads();

    // ---- compute: 256 b's x 8 g's, straight-line, all operands in smem ----
    const u64 v = g_pv[tid];
    const u32 vlo = (u32)v, vhi = (u32)(v >> 32);

    float4* ob = (float4*)out + (size_t)tid * G_DIM + g0;

    #pragma unroll
    for (int gi = 0; gi < G_PER_BLOCK; gi++) {
        const int2 meta = s_meta[gi];

        int cpA = meta.x;
        int cpB = 0x10101010;
        #pragma unroll
        for (int t = 0; t < 8; t++) {
            int4 tw = s_term[gi][t];
            u32 x = ((u32)tw.x & vlo) ^ ((u32)tw.y & vhi);
            cpA += (int)(__popc(x) & 1u) * tw.z;
        }
        #pragma unroll
        for (int t = 8; t < 16; t++) {
            int4 tw = s_term[gi][t];
            u32 x = ((u32)tw.x & vlo) ^ ((u32)tw.y & vhi);
            cpB += (int)(__popc(x) & 1u) * tw.z;
        }
        int cp = cpA + cpB - 0x10101010;

        int b0 = cp & 255;
        int b1 = (cp >> 8) & 255;
        int b2 = (cp >> 16) & 255;
        int b3 = (cp >> 24) & 255;

        int4 A = s_rows[gi][b1];
        int4 B = s_rows[gi][17 + b2];
        int4 C = s_rows[gi][34 + b3];

        int r0 = A.x*B.x - A.y*B.w - A.z*B.z - A.w*B.y;
        int r1 = A.x*B.y + A.y*B.x - A.z*B.w - A.w*B.z;
        int r2 = A.x*B.z + A.y*B.y + A.z*B.x - A.w*B.w;
        int r3 = A.x*B.w + A.y*B.z + A.z*B.y + A.w*B.x;

        int z0 = r0*C.x - r1*C.w - r2*C.z - r3*C.y;
        int z1 = r0*C.y + r1*C.x - r2*C.w - r3*C.z;
        int z2 = r0*C.z + r1*C.y + r2*C.x - r3*C.w;
        int z3 = r0*C.w + r1*C.z + r2*C.y + r3*C.x;

        int sc = (b0 == 0) ? (1 << meta.y) : 0;

        ob[gi] = make_float4((float)(z0 * sc), (float)(z1 * sc),
                             (float)(z2 * sc), (float)(-z3 * sc));
    }
}

// ---------------------------------------------------------------------------
// Launch. Inputs identified BY SIZE (ordering-proof):
//   phases 32768 | params 2097152 | counts 2048 | param_vals 16384 | opp 32
// ---------------------------------------------------------------------------
extern "C" void kernel_launch(void* const* d_in, const int* in_sizes, int n_in,
                              void* d_out, int out_size) {
    const int* phases = nullptr;
    const int* params = nullptr;
    const int* counts = nullptr;
    const int* param_vals = nullptr;

    for (int i = 0; i < n_in; i++) {
        switch (in_sizes[i]) {
            case G_DIM * T_DIM:         phases     = (const int*)d_in[i]; break;
            case G_DIM * T_DIM * P_DIM: params     = (const int*)d_in[i]; break;
            case G_DIM:                 counts     = (const int*)d_in[i]; break;
            case B_DIM * P_DIM:         param_vals = (const int*)d_in[i]; break;
            default: break;  // one_plus_phases (32 floats) — unused
        }
    }

    pack_pv_kernel<<<1, 256>>>(param_vals);
    nodephases_main_kernel<<<G_DIM / G_PER_BLOCK, 256>>>(params, phases, counts,
                                                         (float*)d_out);
}

// round 10
// speedup vs baseline: 1.3024x; 1.1555x over previous
#include <cuda_runtime.h>
#include <cstdint>

typedef unsigned long long u64;
typedef unsigned int u32;

#define G_DIM 2048
#define T_DIM 16
#define B_DIM 256
#define P_DIM 64
#define G_PER_BLOCK 4

// Device-global scratch (no allocations allowed)
__device__ u64  g_pv[B_DIM];
__device__ int4 g_T[3 * 17 * 17];   // g_T[k*289 + a*17 + b] = (1+w^{k+1})^a (1-w^{k+1})^b

// ---------------------------------------------------------------------------
// Ring ops in basis (1, w, w^2, w^3), w^4 = -1.
// ---------------------------------------------------------------------------
__device__ __forceinline__ void ringmul(int* z, const int* x, const int* y) {
    z[0] = x[0]*y[0] - x[1]*y[3] - x[2]*y[2] - x[3]*y[1];
    z[1] = x[0]*y[1] + x[1]*y[0] - x[2]*y[3] - x[3]*y[2];
    z[2] = x[0]*y[2] + x[1]*y[1] + x[2]*y[0] - x[3]*y[3];
    z[3] = x[0]*y[3] + x[1]*y[2] + x[2]*y[1] + x[3]*y[0];
}
__device__ __forceinline__ void ringcpy(int* d, const int* s) {
    d[0] = s[0]; d[1] = s[1]; d[2] = s[2]; d[3] = s[3];
}
__device__ __forceinline__ void ringpow(int* acc, const int* f, int n) {
    int base[4], tmp[4];
    acc[0] = 1; acc[1] = 0; acc[2] = 0; acc[3] = 0;
    ringcpy(base, f);
    while (n) {
        if (n & 1) { ringmul(tmp, acc, base); ringcpy(acc, tmp); }
        n >>= 1;
        if (n) { ringmul(tmp, base, base); ringcpy(base, tmp); }
    }
}
__device__ __forceinline__ int clamp_cnt(int c) {
    return c < 0 ? 0 : (c > T_DIM ? T_DIM : c);
}

// ---------------------------------------------------------------------------
// Init: 12 blocks. Blocks 0..3 build g_T (867 entries, one per thread).
// Blocks 4..11 pack param_vals (8 warps x 4 rows each = 32 rows/block).
// ---------------------------------------------------------------------------
__global__ void init_kernel(const int* __restrict__ param_vals) {
    if (blockIdx.x < 4) {
        int e = blockIdx.x * 256 + threadIdx.x;
        if (e < 3 * 289) {
            int k = e / 289, r = e % 289, a = r / 17, b = r % 17;
            int4 o;
            if (a + b > 16) {
                o = make_int4(0, 0, 0, 0);
            } else {
                int kk = k + 1;
                int fp[4] = {1, 0, 0, 0}; fp[kk] = 1;    // 1 + w^kk
                int fm[4] = {1, 0, 0, 0}; fm[kk] = -1;   // 1 - w^kk
                int pa[4], pb[4], acc[4];
                ringpow(pa, fp, a);
                ringpow(pb, fm, b);
                ringmul(acc, pa, pb);
                o = make_int4(acc[0], acc[1], acc[2], acc[3]);
            }
            g_T[e] = o;
        }
    } else {
        int warp = threadIdx.x >> 5, lane = threadIdx.x & 31;
        int row0 = ((blockIdx.x - 4) * 8 + warp) * 4;
        int a[4], b[4];
        #pragma unroll
        for (int r = 0; r < 4; r++) {
            const int* p = param_vals + (size_t)(row0 + r) * P_DIM;
            a[r] = p[lane]; b[r] = p[lane + 32];
        }
        #pragma unroll
        for (int r = 0; r < 4; r++) {
            u32 lo = __ballot_sync(0xffffffffu, a[r] & 1);
            u32 hi = __ballot_sync(0xffffffffu, b[r] & 1);
            if (lane == 0) g_pv[row0 + r] = ((u64)hi << 32) | (u64)lo;
        }
    }
}

// ---------------------------------------------------------------------------
// Main: 512 blocks x 256 threads; block covers g0..g0+3 for all 256 b's.
// Prologue: 8 warps ballot-pack 64 param rows; warps 0..3 build meta
// (s_pack, m0, m1|m2<<8|m3<<16) and per-term pw. One barrier.
// Compute (per b, per g): branch-free packed-byte-counter parity (2 chains),
// 3 direct L1 lookups into g_T, 2 ring muls, scale, float4 store.
// Output float32 (B, G, 4) in reference basis (1,w,w^2,w^7): c3 = -z3.
// ---------------------------------------------------------------------------
__global__ void __launch_bounds__(256)
nodephases_main_kernel(const int* __restrict__ params,
                       const int* __restrict__ phases,
                       const int* __restrict__ counts,
                       float* __restrict__ out) {
    const int g0   = blockIdx.x * G_PER_BLOCK;
    const int tid  = threadIdx.x;
    const int lane = tid & 31;
    const int warp = tid >> 5;

    __shared__ int4 s_term[G_PER_BLOCK][T_DIM];   // x=lo, y=hi, z=pw
    __shared__ int4 s_meta[G_PER_BLOCK];          // x=s_pack, y=m0, z=m1|m2<<8|m3<<16

    // ---- pack 64 rows: 8 per warp, loads batched for MLP ----
    {
        const int r0 = warp * 8;                  // global row = gi*16 + t
        const int* base = params + ((size_t)g0 * T_DIM + r0) * P_DIM;
        int a[8], b[8];
        #pragma unroll
        for (int i = 0; i < 8; i++) {
            a[i] = base[i * P_DIM + lane];
            b[i] = base[i * P_DIM + 32 + lane];
        }
        #pragma unroll
        for (int i = 0; i < 8; i++) {
            u32 lo = __ballot_sync(0xffffffffu, a[i] & 1);
            u32 hi = __ballot_sync(0xffffffffu, b[i] & 1);
            if (lane == 0) {
                int r = r0 + i;
                s_term[r >> 4][r & 15].x = (int)lo;
                s_term[r >> 4][r & 15].y = (int)hi;
            }
        }
    }

    // ---- meta: warp gi handles g = g0 + gi (warps 0..3) ----
    if (warp < G_PER_BLOCK) {
        const int g = g0 + warp;
        int c = clamp_cnt(counts[g]);
        u32 vm = (c >= 16) ? 0xFFFFu : ((1u << c) - 1u);
        int p  = (lane < 16) ? (phases[g * T_DIM + lane] & 7) : 0;
        int k  = p & 3;
        int sg = (p >> 2) & 1;
        u32 b0m = __ballot_sync(0xffffffffu, k == 0) & vm;
        u32 b1m = __ballot_sync(0xffffffffu, k == 1) & vm;
        u32 b2m = __ballot_sync(0xffffffffu, k == 2) & vm;
        u32 b3m = __ballot_sync(0xffffffffu, k == 3) & vm;
        u32 sgm = __ballot_sync(0xffffffffu, sg == 1) & vm;
        if (lane < 16) {
            int valid = (vm >> lane) & 1;
            s_term[warp][lane].z = valid ? (sg ? -(1 << (8 * k)) : (1 << (8 * k))) : 0;
        }
        if (lane == 0) {
            int s0 = __popc(b0m & sgm), s1 = __popc(b1m & sgm),
                s2 = __popc(b2m & sgm), s3 = __popc(b3m & sgm);
            int m1 = __popc(b1m), m2 = __popc(b2m), m3 = __popc(b3m);
            s_meta[warp] = make_int4(s0 | (s1 << 8) | (s2 << 16) | (s3 << 24),
                                     __popc(b0m),
                                     m1 | (m2 << 8) | (m3 << 16), 0);
        }
    }
    __syncthreads();

    const u64 v = g_pv[tid];
    const u32 vlo = (u32)v, vhi = (u32)(v >> 32);

    float4* ob = (float4*)out + (size_t)tid * G_DIM + g0;

    // ---- compute: 2 g's at a time for ILP without register blowup ----
    #pragma unroll
    for (int pass = 0; pass < G_PER_BLOCK / 2; pass++) {
        int cp[2];
        int4 meta[2];
        #pragma unroll
        for (int j = 0; j < 2; j++) {
            const int gi = pass * 2 + j;
            meta[j] = s_meta[gi];
            int cpA = meta[j].x;
            int cpB = 0x10101010;
            #pragma unroll
            for (int t = 0; t < 8; t++) {
                int4 tw = s_term[gi][t];
                u32 x = ((u32)tw.x & vlo) ^ ((u32)tw.y & vhi);
                cpA += (int)(__popc(x) & 1u) * tw.z;
            }
            #pragma unroll
            for (int t = 8; t < 16; t++) {
                int4 tw = s_term[gi][t];
                u32 x = ((u32)tw.x & vlo) ^ ((u32)tw.y & vhi);
                cpB += (int)(__popc(x) & 1u) * tw.z;
            }
            cp[j] = cpA + cpB - 0x10101010;
        }

        int4 A[2], Bv[2], C[2];
        int  sc[2];
        #pragma unroll
        for (int j = 0; j < 2; j++) {
            int b0 = cp[j] & 255;
            int b1 = (cp[j] >> 8) & 255;
            int b2 = (cp[j] >> 16) & 255;
            int b3 = (cp[j] >> 24) & 255;
            int m1 = meta[j].z & 255;
            int m2 = (meta[j].z >> 8) & 255;
            int m3 = (meta[j].z >> 16) & 255;
            A[j]  = __ldg(&g_T[m1 * 17 - 16 * b1]);
            Bv[j] = __ldg(&g_T[289 + m2 * 17 - 16 * b2]);
            C[j]  = __ldg(&g_T[578 + m3 * 17 - 16 * b3]);
            sc[j] = (b0 == 0) ? (1 << meta[j].y) : 0;
        }

        #pragma unroll
        for (int j = 0; j < 2; j++) {
            int4 a = A[j], b = Bv[j], c = C[j];
            int r0 = a.x*b.x - a.y*b.w - a.z*b.z - a.w*b.y;
            int r1 = a.x*b.y + a.y*b.x - a.z*b.w - a.w*b.z;
            int r2 = a.x*b.z + a.y*b.y + a.z*b.x - a.w*b.w;
            int r3 = a.x*b.w + a.y*b.z + a.z*b.y + a.w*b.x;

            int z0 = r0*c.x - r1*c.w - r2*c.z - r3*c.y;
            int z1 = r0*c.y + r1*c.x - r2*c.w - r3*c.z;
            int z2 = r0*c.z + r1*c.y + r2*c.x - r3*c.w;
            int z3 = r0*c.w + r1*c.z + r2*c.y + r3*c.x;

            int s = sc[j];
            ob[pass * 2 + j] = make_float4((float)(z0 * s), (float)(z1 * s),
                                           (float)(z2 * s), (float)(-z3 * s));
        }
    }
}

// ---------------------------------------------------------------------------
// Launch. Inputs identified BY SIZE (ordering-proof):
//   phases 32768 | params 2097152 | counts 2048 | param_vals 16384 | opp 32
// ---------------------------------------------------------------------------
extern "C" void kernel_launch(void* const* d_in, const int* in_sizes, int n_in,
                              void* d_out, int out_size) {
    const int* phases = nullptr;
    const int* params = nullptr;
    const int* counts = nullptr;
    const int* param_vals = nullptr;

    for (int i = 0; i < n_in; i++) {
        switch (in_sizes[i]) {
            case G_DIM * T_DIM:         phases     = (const int*)d_in[i]; break;
            case G_DIM * T_DIM * P_DIM: params     = (const int*)d_in[i]; break;
            case G_DIM:                 counts     = (const int*)d_in[i]; break;
            case B_DIM * P_DIM:         param_vals = (const int*)d_in[i]; break;
            default: break;  // one_plus_phases (32 floats) — unused
        }
    }

    init_kernel<<<12, 256>>>(param_vals);
    nodephases_main_kernel<<<G_DIM / G_PER_BLOCK, 256>>>(params, phases, counts,
                                                         (float*)d_out);
}

// round 11
// speedup vs baseline: 1.4816x; 1.1376x over previous
#include <cuda_runtime.h>
#include <cstdint>

typedef unsigned long long u64;
typedef unsigned int u32;

#define G_DIM 2048
#define T_DIM 16
#define B_DIM 256
#define P_DIM 64

// Device-global scratch (no allocations allowed)
__device__ u64  g_pv[B_DIM];
__device__ int4 g_T[3 * 17 * 17];   // g_T[k*289 + a*17 + b] = (1+w^{k+1})^a (1-w^{k+1})^b

// ---------------------------------------------------------------------------
// Ring ops in basis (1, w, w^2, w^3), w^4 = -1.
// ---------------------------------------------------------------------------
__device__ __forceinline__ void ringmul(int* z, const int* x, const int* y) {
    z[0] = x[0]*y[0] - x[1]*y[3] - x[2]*y[2] - x[3]*y[1];
    z[1] = x[0]*y[1] + x[1]*y[0] - x[2]*y[3] - x[3]*y[2];
    z[2] = x[0]*y[2] + x[1]*y[1] + x[2]*y[0] - x[3]*y[3];
    z[3] = x[0]*y[3] + x[1]*y[2] + x[2]*y[1] + x[3]*y[0];
}
__device__ __forceinline__ void ringcpy(int* d, const int* s) {
    d[0] = s[0]; d[1] = s[1]; d[2] = s[2]; d[3] = s[3];
}
__device__ __forceinline__ void ringpow(int* acc, const int* f, int n) {
    int base[4], tmp[4];
    acc[0] = 1; acc[1] = 0; acc[2] = 0; acc[3] = 0;
    ringcpy(base, f);
    while (n) {
        if (n & 1) { ringmul(tmp, acc, base); ringcpy(acc, tmp); }
        n >>= 1;
        if (n) { ringmul(tmp, base, base); ringcpy(base, tmp); }
    }
}
__device__ __forceinline__ int clamp_cnt(int c) {
    return c < 0 ? 0 : (c > T_DIM ? T_DIM : c);
}

// ---------------------------------------------------------------------------
// Init: 12 blocks. Blocks 0..3 build g_T (867 entries, one per thread).
// Blocks 4..11 pack param_vals (8 warps x 4 rows each = 32 rows/block).
// ---------------------------------------------------------------------------
__global__ void init_kernel(const int* __restrict__ param_vals) {
    if (blockIdx.x < 4) {
        int e = blockIdx.x * 256 + threadIdx.x;
        if (e < 3 * 289) {
            int k = e / 289, r = e % 289, a = r / 17, b = r % 17;
            int4 o;
            if (a + b > 16) {
                o = make_int4(0, 0, 0, 0);
            } else {
                int kk = k + 1;
                int fp[4] = {1, 0, 0, 0}; fp[kk] = 1;    // 1 + w^kk
                int fm[4] = {1, 0, 0, 0}; fm[kk] = -1;   // 1 - w^kk
                int pa[4], pb[4], acc[4];
                ringpow(pa, fp, a);
                ringpow(pb, fm, b);
                ringmul(acc, pa, pb);
                o = make_int4(acc[0], acc[1], acc[2], acc[3]);
            }
            g_T[e] = o;
        }
    } else {
        int warp = threadIdx.x >> 5, lane = threadIdx.x & 31;
        int row0 = ((blockIdx.x - 4) * 8 + warp) * 4;
        int a[4], b[4];
        #pragma unroll
        for (int r = 0; r < 4; r++) {
            const int* p = param_vals + (size_t)(row0 + r) * P_DIM;
            a[r] = p[lane]; b[r] = p[lane + 32];
        }
        #pragma unroll
        for (int r = 0; r < 4; r++) {
            u32 lo = __ballot_sync(0xffffffffu, a[r] & 1);
            u32 hi = __ballot_sync(0xffffffffu, b[r] & 1);
            if (lane == 0) g_pv[row0 + r] = ((u64)hi << 32) | (u64)lo;
        }
    }
}

// ---------------------------------------------------------------------------
// Main: 2048 blocks x 128 threads. Block = one g; thread handles b = tid and
// b = tid + 128 (term LDS amortized over both).
// Prologue (ONE barrier):
//   all 4 warps: ballot-pack 4 param rows each into s_term.{x,y}
//   warp 0: meta (s_pack, m0) + per-term pw -> s_term[t].z
//   warp kk (1..3): recompute m_kk via ballot, copy row entries b=0..m_kk
//                   from g_T into s_rows[kk-1][b] (1 LDG.128 + STS each).
// Compute: branch-free packed-byte-counter parity (2 chains per b),
//          3 smem row lookups + 2 ring muls per b, scale, float4 store.
// Output float32 (B, G, 4) in reference basis (1,w,w^2,w^7): c3 = -z3.
// ---------------------------------------------------------------------------
__global__ void __launch_bounds__(128)
nodephases_main_kernel(const int* __restrict__ params,
                       const int* __restrict__ phases,
                       const int* __restrict__ counts,
                       float* __restrict__ out) {
    const int g    = blockIdx.x;
    const int tid  = threadIdx.x;
    const int lane = tid & 31;
    const int warp = tid >> 5;

    __shared__ int4 s_term[T_DIM];     // x=lo, y=hi, z=pw
    __shared__ int4 s_rows[3][17];     // staged table rows (class k -> [k-1])
    __shared__ int2 s_meta;            // x=s_pack, y=m0

    // ---- pack: each warp 4 rows, loads batched for MLP ----
    {
        const int* basep = params + (size_t)g * (T_DIM * P_DIM) + warp * 4 * P_DIM;
        int a[4], b[4];
        #pragma unroll
        for (int r = 0; r < 4; r++) {
            a[r] = basep[r * P_DIM + lane];
            b[r] = basep[r * P_DIM + 32 + lane];
        }
        #pragma unroll
        for (int r = 0; r < 4; r++) {
            u32 lo = __ballot_sync(0xffffffffu, a[r] & 1);
            u32 hi = __ballot_sync(0xffffffffu, b[r] & 1);
            if (lane == 0) {
                s_term[warp * 4 + r].x = (int)lo;
                s_term[warp * 4 + r].y = (int)hi;
            }
        }
    }

    // ---- role work (independent across warps; one barrier after) ----
    {
        int c = clamp_cnt(counts[g]);
        u32 vm = (c >= 16) ? 0xFFFFu : ((1u << c) - 1u);
        int p  = (lane < 16) ? (phases[g * T_DIM + lane] & 7) : 0;

        if (warp == 0) {
            int k  = p & 3;
            int sg = (p >> 2) & 1;
            u32 b0m = __ballot_sync(0xffffffffu, k == 0) & vm;
            u32 b1m = __ballot_sync(0xffffffffu, k == 1) & vm;
            u32 b2m = __ballot_sync(0xffffffffu, k == 2) & vm;
            u32 b3m = __ballot_sync(0xffffffffu, k == 3) & vm;
            u32 sgm = __ballot_sync(0xffffffffu, sg == 1) & vm;
            if (lane < 16) {
                int valid = (vm >> lane) & 1;
                s_term[lane].z = valid ? (sg ? -(1 << (8 * k)) : (1 << (8 * k))) : 0;
            }
            if (lane == 0) {
                int s0 = __popc(b0m & sgm), s1 = __popc(b1m & sgm),
                    s2 = __popc(b2m & sgm), s3 = __popc(b3m & sgm);
                s_meta = make_int2(s0 | (s1 << 8) | (s2 << 16) | (s3 << 24),
                                   __popc(b0m));
            }
        } else {
            const int kk = warp;            // class 1..3
            u32 km = __ballot_sync(0xffffffffu, (p & 3) == kk && lane < 16) & vm;
            int m = __popc(km);
            if (lane <= m) {                // b = lane, entry (m-b, b)
                s_rows[kk - 1][lane] = __ldg(&g_T[(kk - 1) * 289 + (m - lane) * 17 + lane]);
            }
        }
    }
    __syncthreads();

    // ---- compute: 2 b's per thread, terms shared ----
    const u64 va = g_pv[tid];
    const u64 vb = g_pv[tid + 128];
    const u32 va_lo = (u32)va, va_hi = (u32)(va >> 32);
    const u32 vb_lo = (u32)vb, vb_hi = (u32)(vb >> 32);

    const int2 meta = s_meta;

    int cpA0 = meta.x, cpB0 = 0x10101010;
    int cpA1 = meta.x, cpB1 = 0x10101010;

    #pragma unroll
    for (int t = 0; t < 8; t++) {
        int4 tw = s_term[t];
        u32 x0 = ((u32)tw.x & va_lo) ^ ((u32)tw.y & va_hi);
        u32 x1 = ((u32)tw.x & vb_lo) ^ ((u32)tw.y & vb_hi);
        cpA0 += (int)(__popc(x0) & 1u) * tw.z;
        cpA1 += (int)(__popc(x1) & 1u) * tw.z;
    }
    #pragma unroll
    for (int t = 8; t < 16; t++) {
        int4 tw = s_term[t];
        u32 x0 = ((u32)tw.x & va_lo) ^ ((u32)tw.y & va_hi);
        u32 x1 = ((u32)tw.x & vb_lo) ^ ((u32)tw.y & vb_hi);
        cpB0 += (int)(__popc(x0) & 1u) * tw.z;
        cpB1 += (int)(__popc(x1) & 1u) * tw.z;
    }

    const int cp[2] = { cpA0 + cpB0 - 0x10101010, cpA1 + cpB1 - 0x10101010 };
    const int bb[2] = { tid, tid + 128 };

    #pragma unroll
    for (int j = 0; j < 2; j++) {
        int b0 = cp[j] & 255;
        int b1 = (cp[j] >> 8) & 255;
        int b2 = (cp[j] >> 16) & 255;
        int b3 = (cp[j] >> 24) & 255;

        int4 A = s_rows[0][b1];
        int4 B = s_rows[1][b2];
        int4 C = s_rows[2][b3];

        int r0 = A.x*B.x - A.y*B.w - A.z*B.z - A.w*B.y;
        int r1 = A.x*B.y + A.y*B.x - A.z*B.w - A.w*B.z;
        int r2 = A.x*B.z + A.y*B.y + A.z*B.x - A.w*B.w;
        int r3 = A.x*B.w + A.y*B.z + A.z*B.y + A.w*B.x;

        int z0 = r0*C.x - r1*C.w - r2*C.z - r3*C.y;
        int z1 = r0*C.y + r1*C.x - r2*C.w - r3*C.z;
        int z2 = r0*C.z + r1*C.y + r2*C.x - r3*C.w;
        int z3 = r0*C.w + r1*C.z + r2*C.y + r3*C.x;

        int sc = (b0 == 0) ? (1 << meta.y) : 0;

        float4* o = (float4*)out + (size_t)bb[j] * G_DIM + g;
        *o = make_float4((float)(z0 * sc), (float)(z1 * sc),
                         (float)(z2 * sc), (float)(-z3 * sc));
    }
}

// ---------------------------------------------------------------------------
// Launch. Inputs identified BY SIZE (ordering-proof):
//   phases 32768 | params 2097152 | counts 2048 | param_vals 16384 | opp 32
// ---------------------------------------------------------------------------
extern "C" void kernel_launch(void* const* d_in, const int* in_sizes, int n_in,
                              void* d_out, int out_size) {
    const int* phases = nullptr;
    const int* params = nullptr;
    const int* counts = nullptr;
    const int* param_vals = nullptr;

    for (int i = 0; i < n_in; i++) {
        switch (in_sizes[i]) {
            case G_DIM * T_DIM:         phases     = (const int*)d_in[i]; break;
            case G_DIM * T_DIM * P_DIM: params     = (const int*)d_in[i]; break;
            case G_DIM:                 counts     = (const int*)d_in[i]; break;
            case B_DIM * P_DIM:         param_vals = (const int*)d_in[i]; break;
            default: break;  // one_plus_phases (32 floats) — unused
        }
    }

    init_kernel<<<12, 256>>>(param_vals);
    nodephases_main_kernel<<<G_DIM, 128>>>(params, phases, counts, (float*)d_out);
}